// round 11
// baseline (speedup 1.0000x reference)
#include <cuda_runtime.h>
#include <math.h>
#include <stdint.h>

#define Bn  128
#define NAn 8
#define ADn 16
#define DMn 512
#define DIn 1024
#define DSn 32
#define DRn 32
#define NBn 4
#define ODn 128
#define NBLK 128
#define NTHR 512

// ---------------- persistent scratch (no allocations allowed) ----------------
__device__ float g_x[Bn*DMn];
__device__ float g_ctx[Bn*DMn];
__device__ float g_xn[Bn*DMn];
__device__ float g_xc[Bn*DIn];
__device__ float g_sz[Bn*DIn];
__device__ float g_ys[Bn*DIn];
__device__ float g_aprev[Bn*ADn];
__device__ float g_part[4][Bn*DMn];
__device__ float g_dbcp[8][Bn*96];
__device__ float g_hist[8*4*Bn*DIn];
__device__ float g_negeA[8*DIn*DSn];
__device__ float g_h[(size_t)8*DSn*Bn*DIn];
__device__ unsigned g_barA;   // zero-init
__device__ unsigned g_barG;   // zero-init

__device__ __forceinline__ float sigmoidf_(float x){ return 1.f/(1.f+__expf(-x)); }
__device__ __forceinline__ float siluf_(float x){ return x*sigmoidf_(x); }
__device__ __forceinline__ float softplusf_(float x){ return (x>20.f)? x : log1pf(__expf(x)); }

__device__ __forceinline__ uint32_t tf32h(float x){
  uint32_t r; asm("cvt.rna.tf32.f32 %0, %1;" : "=r"(r) : "f"(x)); return r;
}
__device__ __forceinline__ void mma_tf32(float c[4], uint32_t a0,uint32_t a1,uint32_t a2,uint32_t a3,
                                         uint32_t b0,uint32_t b1){
  asm volatile("mma.sync.aligned.m16n8k8.row.col.f32.tf32.tf32.f32 "
    "{%0,%1,%2,%3},{%4,%5,%6,%7},{%8,%9},{%0,%1,%2,%3};"
    : "+f"(c[0]),"+f"(c[1]),"+f"(c[2]),"+f"(c[3])
    : "r"(a0),"r"(a1),"r"(a2),"r"(a3),"r"(b0),"r"(b1));
}

// ---------------- software grid barrier (all NBLK blocks resident) ----------------
__device__ __forceinline__ void gridbar(){
  __syncthreads();
  if (threadIdx.x == 0){
    __threadfence();
    unsigned g = *((volatile unsigned*)&g_barG);
    if (atomicAdd(&g_barA, 1u) == NBLK-1u){
      *((volatile unsigned*)&g_barA) = 0u;
      __threadfence();
      *((volatile unsigned*)&g_barG) = g + 1u;
    } else {
      while (*((volatile unsigned*)&g_barG) == g) {}
      __threadfence();
    }
  }
  __syncthreads();
}

// ---------------- block-wide LayerNorm stats over 512 values (1/thread) ----------------
__device__ __forceinline__ float2 blockLN(float x, float* red, int t){
  float s = x, q = x*x;
  #pragma unroll
  for (int o=16;o;o>>=1){ s+=__shfl_xor_sync(0xffffffffu,s,o); q+=__shfl_xor_sync(0xffffffffu,q,o); }
  if ((t&31)==0){ red[t>>5]=s; red[16+(t>>5)]=q; }
  __syncthreads();
  if (t==0){
    float S=0,Q=0;
    #pragma unroll
    for (int w=0;w<16;w++){ S+=red[w]; Q+=red[16+w]; }
    float m=S*(1.f/DMn);
    red[32]=m; red[33]=rsqrtf(Q*(1.f/DMn)-m*m+1e-5f);
  }
  __syncthreads();
  float2 r = make_float2(red[32], red[33]);
  __syncthreads();
  return r;
}

// ============ tf32 3-term warp-MMA GEMM: 32m x 64n block tile, K chunks of 32 ============
// sm layout per chunk buffer (single-buffered, 6528 floats):
//   Ah[32][34] @0, Al[32][34] @1088, Bh[32][68] @2176, Bl[32][68] @4352
// A loaded via __ldcg (mutable activations), B via normal loads (weights).
__device__ __forceinline__ void gemm32x64(float* sm, int t,
    const float* __restrict__ Ag, int lda,
    const float* __restrict__ Bg, int ldb,
    int K, float c[4]){
  int arow = t>>4, ak = (t&15)*2;
  int brow = t>>4, bc4 = (t&15)*4;
  int w = t>>5, lane = t&31;
  int wm = w&1, wn = w>>1;
  int gid = lane>>2, tg = lane&3;
  float* Ah = sm;        float* Al = sm + 1088;
  float* Bh = sm + 2176; float* Bl = sm + 4352;
  c[0]=c[1]=c[2]=c[3]=0.f;
  float2 pa = __ldcg((const float2*)(Ag + arow*lda + ak));
  float4 pb = *(const float4*)(Bg + (size_t)brow*ldb + bc4);
  for (int kc=0; kc<K; kc+=32){
    if (kc) __syncthreads();               // prior compute done before overwrite
    { uint32_t h0 = tf32h(pa.x), h1 = tf32h(pa.y);
      float l0 = pa.x - __uint_as_float(h0), l1 = pa.y - __uint_as_float(h1);
      *(float2*)&Ah[arow*34+ak] = make_float2(__uint_as_float(h0), __uint_as_float(h1));
      *(float2*)&Al[arow*34+ak] = make_float2(__uint_as_float(tf32h(l0)), __uint_as_float(tf32h(l1)));
      uint32_t q0=tf32h(pb.x), q1=tf32h(pb.y), q2=tf32h(pb.z), q3=tf32h(pb.w);
      float m0=pb.x-__uint_as_float(q0), m1=pb.y-__uint_as_float(q1);
      float m2=pb.z-__uint_as_float(q2), m3=pb.w-__uint_as_float(q3);
      *(float4*)&Bh[brow*68+bc4] = make_float4(__uint_as_float(q0),__uint_as_float(q1),
                                               __uint_as_float(q2),__uint_as_float(q3));
      *(float4*)&Bl[brow*68+bc4] = make_float4(__uint_as_float(tf32h(m0)),__uint_as_float(tf32h(m1)),
                                               __uint_as_float(tf32h(m2)),__uint_as_float(tf32h(m3)));
    }
    __syncthreads();
    if (kc+32 < K){
      pa = __ldcg((const float2*)(Ag + arow*lda + kc+32 + ak));
      pb = *(const float4*)(Bg + (size_t)(kc+32+brow)*ldb + bc4);
    }
    #pragma unroll
    for (int kk=0; kk<32; kk+=8){
      int ab = (wm*16+gid)*34 + kk + tg;
      uint32_t a0h=__float_as_uint(Ah[ab]),   a1h=__float_as_uint(Ah[ab+8*34]);
      uint32_t a2h=__float_as_uint(Ah[ab+4]), a3h=__float_as_uint(Ah[ab+4+8*34]);
      uint32_t a0l=__float_as_uint(Al[ab]),   a1l=__float_as_uint(Al[ab+8*34]);
      uint32_t a2l=__float_as_uint(Al[ab+4]), a3l=__float_as_uint(Al[ab+4+8*34]);
      int bb = (kk+tg)*68 + wn*8 + gid;
      uint32_t b0h=__float_as_uint(Bh[bb]), b1h=__float_as_uint(Bh[bb+4*68]);
      uint32_t b0l=__float_as_uint(Bl[bb]), b1l=__float_as_uint(Bl[bb+4*68]);
      mma_tf32(c, a0h,a1h,a2h,a3h, b0h,b1h);   // Ah*Bh
      mma_tf32(c, a0l,a1l,a2l,a3l, b0h,b1h);   // Al*Bh
      mma_tf32(c, a0h,a1h,a2h,a3h, b0l,b1l);   // Ah*Bl
    }
  }
  __syncthreads();
}

// ---------------- phase: embed + ctx + LN -> g_xn ----------------
__device__ __forceinline__ void phaseEmbed(float* sm, int bid, int t,
    const float* __restrict__ obs_rep, const float* __restrict__ obs,
    const float* __restrict__ We, const float* __restrict__ be,
    const float* __restrict__ Wo, const float* __restrict__ ln0, int i){
  float* sobs = sm;
  float* sap  = sm + 128;
  float* red  = sm + 160;
  int b = bid;
  if (t < ODn) sobs[t] = obs[(b*NAn+i)*ODn + t];
  if (i > 0 && t < ADn) sap[t] = __ldcg(&g_aprev[b*ADn + t]);
  __syncthreads();
  int c = t;
  float x = be[c];
  if (i > 0){
    #pragma unroll
    for (int a=0;a<ADn;a++) x += sap[a]*We[a*DMn + c];
  }
  float cv = obs_rep[(b*NAn+i)*DMn + c];
  #pragma unroll 4
  for (int o=0;o<ODn;o++) cv += sobs[o]*Wo[o*DMn + c];
  __stcg(&g_x[b*DMn + c], x);
  __stcg(&g_ctx[b*DMn + c], cv);
  float2 mr = blockLN(x, red, t);
  __stcg(&g_xn[b*DMn + c], (x-mr.x)*mr.y*ln0[c]);
}

// ---------------- phase A: xn[128,512]@Win[512,2048] (tf32 mma) + conv/silu epilogue ----------------
__device__ __forceinline__ void phaseA(float* sm, int bid, int t,
    const float* __restrict__ Win, const float* __restrict__ cw,
    const float* __restrict__ cb, int inst, int step){
  int m0 = (bid>>5)*32, n0 = (bid&31)*64;
  float c[4];
  gemm32x64(sm, t, g_xn + m0*DMn, DMn, Win + n0, 2*DIn, DMn, c);
  int w=t>>5, lane=t&31, wm=w&1, wn=w>>1, gid=lane>>2, tg=lane&3;
  int slot = step & 3;
  #pragma unroll
  for (int r=0;r<2;r++){
    int m = m0 + wm*16 + gid + 8*r;
    int n = n0 + wn*8 + 2*tg;
    float v0 = c[2*r], v1 = c[2*r+1];
    if (n0 < DIn){
      int d = n;
      __stcg((float2*)&g_hist[((inst*4+slot)*Bn + m)*DIn + d], make_float2(v0,v1));
      float2 w3 = *(const float2*)&cw[3*DIn+d];
      float2 cbv = *(const float2*)&cb[d];
      float cx = cbv.x + w3.x*v0, cy = cbv.y + w3.y*v1;
      if (step>=1){ float2 h1=__ldcg((const float2*)&g_hist[((inst*4+((step-1)&3))*Bn+m)*DIn+d]);
                    float2 wv=*(const float2*)&cw[2*DIn+d]; cx+=wv.x*h1.x; cy+=wv.y*h1.y; }
      if (step>=2){ float2 h2=__ldcg((const float2*)&g_hist[((inst*4+((step-2)&3))*Bn+m)*DIn+d]);
                    float2 wv=*(const float2*)&cw[1*DIn+d]; cx+=wv.x*h2.x; cy+=wv.y*h2.y; }
      if (step>=3){ float2 h3=__ldcg((const float2*)&g_hist[((inst*4+((step-3)&3))*Bn+m)*DIn+d]);
                    float2 wv=*(const float2*)&cw[0*DIn+d]; cx+=wv.x*h3.x; cy+=wv.y*h3.y; }
      __stcg((float2*)&g_xc[m*DIn+d], make_float2(siluf_(cx), siluf_(cy)));
    } else {
      int d = n - DIn;
      __stcg((float2*)&g_sz[m*DIn+d], make_float2(siluf_(v0), siluf_(v1)));
    }
  }
}

// ---------------- phase B1: dbc partials, xc[128,1024]@Wx[1024,96], split-K=8 ----------------
__device__ __forceinline__ void phaseB1(float* sm, int bid, int t,
    const float* __restrict__ Wx){
  if (bid >= 32) return;
  float* As = sm;          // [32][33]
  float* Bs = sm + 1056;   // [32][96]
  int m0 = (bid>>3)*32, kz = bid&7, k0 = kz*128;
  int ty = t>>4, tx6 = (t&15)*6;
  int lr = t>>4, lc2 = (t&15)*2;
  float a0r, a1r; float2 w0r, w1r, w2r;
  { float2 av = __ldcg((const float2*)&g_xc[(m0+lr)*DIn + k0 + lc2]);
    a0r=av.x; a1r=av.y;
    const float* wb = &Wx[(k0+lr)*96 + tx6];
    w0r = *(const float2*)(wb+0); w1r = *(const float2*)(wb+2); w2r = *(const float2*)(wb+4); }
  float acc[6] = {0,0,0,0,0,0};
  for (int kc=0; kc<128; kc+=32){
    As[lc2*33+lr]=a0r; As[(lc2+1)*33+lr]=a1r;
    { float* bb = &Bs[lr*96 + tx6];
      *(float2*)(bb+0)=w0r; *(float2*)(bb+2)=w1r; *(float2*)(bb+4)=w2r; }
    __syncthreads();
    if (kc+32 < 128){
      float2 av = __ldcg((const float2*)&g_xc[(m0+lr)*DIn + k0 + kc+32 + lc2]);
      a0r=av.x; a1r=av.y;
      const float* wb = &Wx[(k0+kc+32+lr)*96 + tx6];
      w0r = *(const float2*)(wb+0); w1r = *(const float2*)(wb+2); w2r = *(const float2*)(wb+4);
    }
    #pragma unroll
    for (int k=0;k<32;k++){
      float a = As[k*33+ty];
      #pragma unroll
      for (int j=0;j<6;j++) acc[j] += a*Bs[k*96+tx6+j];
    }
    __syncthreads();
  }
  #pragma unroll
  for (int j=0;j<6;j++) __stcg(&g_dbcp[kz][(m0+ty)*96 + tx6 + j], acc[j]);
}

// ---------------- phase B2: reduce dbc -> delta -> SSM -> y*silu(z) ----------------
__device__ __forceinline__ void phaseB2(float* sm, int bid, int t,
    const float* __restrict__ Wdt, const float* __restrict__ dtb,
    const float* __restrict__ Dp, int inst, int step){
  float* sdbc = sm;          // [32][96]
  float* sWdt = sm + 3072;   // [32][32]
  float* snA  = sm + 4096;   // [32][32]
  int d0 = (bid&31)*32, b0 = (bid>>5)*32;
  #pragma unroll
  for (int u=0;u<2;u++){
    int e = t + 512*u;
    int r = e>>5, c = e&31;
    sWdt[r*32+c] = Wdt[r*DIn + d0 + c];
    snA[r*32+c]  = __ldcg(&g_negeA[inst*DIn*DSn + r*DIn + d0 + c]);
  }
  #pragma unroll
  for (int u=0;u<6;u++){
    int e = t + 512*u;
    int rr = e/96, cc = e - rr*96;
    float s = 0.f;
    #pragma unroll
    for (int p=0;p<8;p++) s += __ldcg(&g_dbcp[p][(b0+rr)*96 + cc]);
    sdbc[rr*96+cc] = s;
  }
  __syncthreads();
  int lane = t&31, br = t>>5;
  #pragma unroll
  for (int rep=0;rep<2;rep++){
    int brow = br + 16*rep;
    int b = b0 + brow, d = d0 + lane;
    float acc = dtb[d];
    #pragma unroll
    for (int r=0;r<DRn;r++) acc += sdbc[brow*96+r]*sWdt[r*32+lane];
    float delta = softplusf_(acc);
    float xc = __ldcg(&g_xc[b*DIn + d]);
    float dxc = delta*xc;
    float* hb = g_h + (size_t)inst*DSn*Bn*DIn + (size_t)b*DIn + d;
    float y = 0.f;
    #pragma unroll
    for (int s=0;s<DSn;s++){
      float dA = __expf(delta * snA[s*32+lane]);
      float hv = (step>0) ? __ldcg(&hb[(size_t)s*(Bn*DIn)]) : 0.f;
      hv = dA*hv + dxc*sdbc[brow*96+32+s];
      __stcg(&hb[(size_t)s*(Bn*DIn)], hv);
      y += hv*sdbc[brow*96+64+s];
    }
    y += Dp[d]*xc;
    __stcg(&g_ys[b*DIn + d], y*__ldcg(&g_sz[b*DIn + d]));
  }
  __syncthreads();
}

// ---------------- phase D: ys[128,1024]@Wout[1024,512] (tf32 mma), split-K=4 ----------------
__device__ __forceinline__ void phaseD(float* sm, int bid, int t,
    const float* __restrict__ Wout){
  int n0 = (bid&7)*64, m0 = ((bid>>3)&3)*32, kz = bid>>5;
  int k0 = kz*256;
  float c[4];
  gemm32x64(sm, t, g_ys + m0*DIn + k0, DIn, Wout + (size_t)k0*DMn + n0, DMn, 256, c);
  int w=t>>5, lane=t&31, wm=w&1, wn=w>>1, gid=lane>>2, tg=lane&3;
  float* P = g_part[kz];
  int n = n0 + wn*8 + 2*tg;
  int m = m0 + wm*16 + gid;
  __stcg((float2*)&P[m*DMn + n],     make_float2(c[0],c[1]));
  __stcg((float2*)&P[(m+8)*DMn + n], make_float2(c[2],c[3]));
}

// ---------------- phase AddLN: x += sum partials; g_xn = LN(x)*lnw (+ctx) ----------------
__device__ __forceinline__ void phaseAddLN(float* sm, int bid, int t,
    const float* __restrict__ lnw, int useCtx){
  float* red = sm;
  int b = bid, c = t;
  float x = __ldcg(&g_x[b*DMn + c]);
  #pragma unroll
  for (int p=0;p<4;p++) x += __ldcg(&g_part[p][b*DMn + c]);
  __stcg(&g_x[b*DMn + c], x);
  float2 mr = blockLN(x, red, t);
  float xn = (x-mr.x)*mr.y*lnw[c];
  if (useCtx) xn += __ldcg(&g_ctx[b*DMn + c]);
  __stcg(&g_xn[b*DMn + c], xn);
}

// ---------------- phase Head: head GEMM + raw/act/logprob ----------------
__device__ __forceinline__ void phaseHead(float* sm, int bid, int t,
    const float* __restrict__ Wh, const float* __restrict__ lstd,
    const float* __restrict__ eps, float* __restrict__ out, int i){
  float* sxn   = sm;
  float* spart = sm + 512;
  int b = bid;
  sxn[t] = __ldcg(&g_xn[b*DMn + t]);
  __syncthreads();
  int seg = t>>4, j = t&15;
  float p = 0.f;
  #pragma unroll 4
  for (int k=seg*16; k<seg*16+16; k++) p += sxn[k]*Wh[k*ADn + j];
  spart[t] = p;
  __syncthreads();
  if (t < 16){
    float m = 0.f;
    #pragma unroll
    for (int sg=0;sg<32;sg++) m += spart[sg*16 + t];
    float std = softplusf_(lstd[t]);
    float e = eps[(b*NAn+i)*ADn + t];
    float raw = m + std*e;
    float act = tanhf(raw);
    int oidx = (b*NAn+i)*ADn + t;
    out[oidx] = act;
    out[17408 + oidx] = raw;
    __stcg(&g_aprev[b*ADn + t], act);
    float term = -0.5f*e*e - logf(std)
               - 2.f*(0.69314718055994531f - raw - softplusf_(-2.f*raw));
    #pragma unroll
    for (int o=8;o;o>>=1) term += __shfl_xor_sync(0xffffu, term, o);
    if (t==0) out[16384 + b*NAn + i] = term - 0.5f*ADn*1.8378770664093453f;
  }
  __syncthreads();
}

// ---------------- the megakernel ----------------
__global__ void __launch_bounds__(NTHR, 1) mega(
    const float* __restrict__ obs_rep, const float* __restrict__ obs,
    const float* __restrict__ eps,
    const float* __restrict__ We, const float* __restrict__ be,
    const float* __restrict__ Wo,
    const float* __restrict__ ln1, const float* __restrict__ ln2,
    const float* __restrict__ ln_out,
    const float* __restrict__ Wh, const float* __restrict__ lstd,
    const float* __restrict__ ip_s, const float* __restrict__ cw_s,
    const float* __restrict__ cb_s, const float* __restrict__ xp_s,
    const float* __restrict__ dt_s, const float* __restrict__ dtb_s,
    const float* __restrict__ al_s, const float* __restrict__ D_s,
    const float* __restrict__ op_s,
    const float* __restrict__ ip_c, const float* __restrict__ cw_c,
    const float* __restrict__ cb_c, const float* __restrict__ xp_c,
    const float* __restrict__ dt_c, const float* __restrict__ dtb_c,
    const float* __restrict__ al_c, const float* __restrict__ D_c,
    const float* __restrict__ op_c,
    float* __restrict__ out){
  __shared__ __align__(16) float sm[6528];
  int bid = blockIdx.x, t = threadIdx.x;

  // prep: -exp(A_log) transposed
  for (int idx = bid*NTHR + t; idx < 8*DIn*DSn; idx += NBLK*NTHR){
    int inst = idx >> 15;
    int e = idx & 32767;
    int d = e >> 5, s = e & 31;
    int v = inst & 1, nb = inst >> 1;
    const float* src = (v ? al_c : al_s) + nb*DIn*DSn;
    __stcg(&g_negeA[inst*DIn*DSn + s*DIn + d], -__expf(src[d*DSn + s]));
  }
  gridbar();

  for (int i=0;i<NAn;i++){
    phaseEmbed(sm, bid, t, obs_rep, obs, We, be, Wo, ln1, i);
    gridbar();
    for (int cell=0; cell<8; cell++){
      int nb = cell>>1, v = cell&1;
      const float* Win  = (v? ip_c : ip_s) + (size_t)nb*DMn*2*DIn;
      const float* cw   = (v? cw_c : cw_s) + nb*4*DIn;
      const float* cb   = (v? cb_c : cb_s) + nb*DIn;
      const float* Wx   = (v? xp_c : xp_s) + (size_t)nb*DIn*96;
      const float* Wdt  = (v? dt_c : dt_s) + nb*DRn*DIn;
      const float* dtb  = (v? dtb_c: dtb_s)+ nb*DIn;
      const float* Dp   = (v? D_c  : D_s)  + nb*DIn;
      const float* Wout = (v? op_c : op_s) + (size_t)nb*DIn*DMn;

      phaseA(sm, bid, t, Win, cw, cb, cell, i);
      gridbar();
      phaseB1(sm, bid, t, Wx);
      gridbar();
      phaseB2(sm, bid, t, Wdt, dtb, Dp, cell, i);
      gridbar();
      phaseD(sm, bid, t, Wout);
      gridbar();
      const float* lnw; int uc;
      if (v==0){ lnw = ln2 + nb*DMn; uc = 1; }
      else if (nb < NBn-1){ lnw = ln1 + (nb+1)*DMn; uc = 0; }
      else { lnw = ln_out; uc = 0; }
      phaseAddLN(sm, bid, t, lnw, uc);
      gridbar();
    }
    phaseHead(sm, bid, t, Wh, lstd, eps, out, i);
    gridbar();
  }
}

extern "C" void kernel_launch(void* const* d_in, const int* in_sizes, int n_in,
                              void* d_out, int out_size){
  (void)in_sizes; (void)n_in; (void)out_size;
  mega<<<NBLK, NTHR>>>(
    (const float*)d_in[0],  (const float*)d_in[1],  (const float*)d_in[2],
    (const float*)d_in[3],  (const float*)d_in[4],  (const float*)d_in[5],
    (const float*)d_in[6],  (const float*)d_in[7],  (const float*)d_in[8],
    (const float*)d_in[9],  (const float*)d_in[10],
    (const float*)d_in[11], (const float*)d_in[12], (const float*)d_in[13],
    (const float*)d_in[14], (const float*)d_in[15], (const float*)d_in[16],
    (const float*)d_in[17], (const float*)d_in[18], (const float*)d_in[19],
    (const float*)d_in[20], (const float*)d_in[21], (const float*)d_in[22],
    (const float*)d_in[23], (const float*)d_in[24], (const float*)d_in[25],
    (const float*)d_in[26], (const float*)d_in[27], (const float*)d_in[28],
    (float*)d_out);
}

// round 12
// speedup vs baseline: 1.2705x; 1.2705x over previous
#include <cuda_runtime.h>
#include <math.h>
#include <stdint.h>

#define Bn  128
#define NAn 8
#define ADn 16
#define DMn 512
#define DIn 1024
#define DSn 32
#define DRn 32
#define NBn 4
#define ODn 128
#define NBLK 128
#define NTHR 512

// ---------------- persistent scratch (no allocations allowed) ----------------
__device__ float g_x[Bn*DMn];
__device__ float g_ctx[Bn*DMn];
__device__ float g_xn[Bn*DMn];
__device__ float g_xc[Bn*DIn];
__device__ float g_sz[Bn*DIn];
__device__ float g_ys[Bn*DIn];
__device__ float g_aprev[Bn*ADn];
__device__ float g_part[4][Bn*DMn];
__device__ float g_dbcp[16][Bn*96];
__device__ float g_hist[8*4*Bn*DIn];
__device__ float g_negeA[8*DIn*DSn];
__device__ float g_h[(size_t)8*DSn*Bn*DIn];
__device__ volatile unsigned g_flags[NBLK];  // zero-init
__device__ volatile unsigned g_gen;          // zero-init

__device__ __forceinline__ float sigmoidf_(float x){ return 1.f/(1.f+__expf(-x)); }
__device__ __forceinline__ float siluf_(float x){ return x*sigmoidf_(x); }
__device__ __forceinline__ float softplusf_(float x){ return (x>20.f)? x : log1pf(__expf(x)); }

__device__ __forceinline__ uint32_t tf32h(float x){
  uint32_t r; asm("cvt.rna.tf32.f32 %0, %1;" : "=r"(r) : "f"(x)); return r;
}
__device__ __forceinline__ void mma_tf32(float c[4], uint32_t a0,uint32_t a1,uint32_t a2,uint32_t a3,
                                         uint32_t b0,uint32_t b1){
  asm volatile("mma.sync.aligned.m16n8k8.row.col.f32.tf32.tf32.f32 "
    "{%0,%1,%2,%3},{%4,%5,%6,%7},{%8,%9},{%0,%1,%2,%3};"
    : "+f"(c[0]),"+f"(c[1]),"+f"(c[2]),"+f"(c[3])
    : "r"(a0),"r"(a1),"r"(a2),"r"(a3),"r"(b0),"r"(b1));
}

__device__ __forceinline__ void cp16(float* dst, const float* src){
  unsigned d = (unsigned)__cvta_generic_to_shared(dst);
  asm volatile("cp.async.cg.shared.global [%0], [%1], 16;" :: "r"(d), "l"(src));
}
__device__ __forceinline__ void cpcommit(){ asm volatile("cp.async.commit_group;" ::: "memory"); }

// ---------------- flag-array grid barrier (no atomic contention) ----------------
__device__ __forceinline__ void gridbar(unsigned& gen, int bid, int t){
  __syncthreads();
  gen++;
  if (t == 0){ __threadfence(); g_flags[bid] = gen; }
  if (bid == 0){
    if (t < NBLK){ while (g_flags[t] < gen) {} }
    __syncthreads();
    if (t == 0){ __threadfence(); g_gen = gen; }
  } else {
    if (t == 0){ while (g_gen < gen) {} __threadfence(); }
  }
  __syncthreads();
}

// ---------------- block-wide LayerNorm stats over 512 values (1/thread) ----------------
__device__ __forceinline__ float2 blockLN(float x, float* red, int t){
  float s = x, q = x*x;
  #pragma unroll
  for (int o=16;o;o>>=1){ s+=__shfl_xor_sync(0xffffffffu,s,o); q+=__shfl_xor_sync(0xffffffffu,q,o); }
  if ((t&31)==0){ red[t>>5]=s; red[16+(t>>5)]=q; }
  __syncthreads();
  if (t==0){
    float S=0,Q=0;
    #pragma unroll
    for (int w=0;w<16;w++){ S+=red[w]; Q+=red[16+w]; }
    float m=S*(1.f/DMn);
    red[32]=m; red[33]=rsqrtf(Q*(1.f/DMn)-m*m+1e-5f);
  }
  __syncthreads();
  float2 r = make_float2(red[32], red[33]);
  __syncthreads();
  return r;
}

// ============ tf32 3-term MMA GEMM, 32m x 64n tile, cp.async 3-stage K pipeline ============
// smem: A stages 3 x [32][36] @0..3456, B stages 3 x [32][68] @3456..9984
__device__ __forceinline__ void gemm32x64(float* sm, int t,
    const float* __restrict__ Ag, int lda,
    const float* __restrict__ Bg, int ldb,
    int K, float c[4]){
  const int ASZ = 32*36, BSZ = 32*68;
  float* Abase = sm;
  float* Bbase = sm + 3*ASZ;
  int w=t>>5, lane=t&31, wm=w&1, wn=w>>1, gid=lane>>2, tg=lane&3;
  c[0]=c[1]=c[2]=c[3]=0.f;
  int nch = K>>5;
  #pragma unroll
  for (int s=0;s<2;s++){
    int kc = s*32;
    if (t<256){ int r=t>>3, c4=(t&7)*4; cp16(Abase+s*ASZ + r*36 + c4, Ag + r*lda + kc + c4); }
    { int r=t>>4, c4=(t&15)*4; cp16(Bbase+s*BSZ + r*68 + c4, Bg + (size_t)(kc+r)*ldb + c4); }
    cpcommit();
  }
  for (int ci=0; ci<nch; ci++){
    if (ci+2 < nch) asm volatile("cp.async.wait_group 1;" ::: "memory");
    else            asm volatile("cp.async.wait_group 0;" ::: "memory");
    __syncthreads();
    if (ci+2 < nch){
      int s = (ci+2)%3, kc = (ci+2)*32;
      if (t<256){ int r=t>>3, c4=(t&7)*4; cp16(Abase+s*ASZ + r*36 + c4, Ag + r*lda + kc + c4); }
      { int r=t>>4, c4=(t&15)*4; cp16(Bbase+s*BSZ + r*68 + c4, Bg + (size_t)(kc+r)*ldb + c4); }
      cpcommit();
    }
    const float* As = Abase + (ci%3)*ASZ;
    const float* Bs = Bbase + (ci%3)*BSZ;
    #pragma unroll
    for (int kk=0; kk<32; kk+=8){
      float a0f=As[(wm*16+gid)*36 + kk+tg],   a1f=As[(wm*16+gid+8)*36 + kk+tg];
      float a2f=As[(wm*16+gid)*36 + kk+tg+4], a3f=As[(wm*16+gid+8)*36 + kk+tg+4];
      float b0f=Bs[(kk+tg)*68 + wn*8 + gid],  b1f=Bs[(kk+tg+4)*68 + wn*8 + gid];
      uint32_t a0h=tf32h(a0f), a1h=tf32h(a1f), a2h=tf32h(a2f), a3h=tf32h(a3f);
      uint32_t b0h=tf32h(b0f), b1h=tf32h(b1f);
      uint32_t a0l=tf32h(a0f-__uint_as_float(a0h)), a1l=tf32h(a1f-__uint_as_float(a1h));
      uint32_t a2l=tf32h(a2f-__uint_as_float(a2h)), a3l=tf32h(a3f-__uint_as_float(a3h));
      uint32_t b0l=tf32h(b0f-__uint_as_float(b0h)), b1l=tf32h(b1f-__uint_as_float(b1h));
      mma_tf32(c, a0h,a1h,a2h,a3h, b0h,b1h);
      mma_tf32(c, a0l,a1l,a2l,a3l, b0h,b1h);
      mma_tf32(c, a0h,a1h,a2h,a3h, b0l,b1l);
    }
    __syncthreads();
  }
}

// ---------------- phase: embed + ctx + LN -> g_xn ----------------
__device__ __forceinline__ void phaseEmbed(float* sm, int bid, int t,
    const float* __restrict__ obs_rep, const float* __restrict__ obs,
    const float* __restrict__ We, const float* __restrict__ be,
    const float* __restrict__ Wo, const float* __restrict__ ln0, int i){
  float* sobs = sm;
  float* sap  = sm + 128;
  float* red  = sm + 160;
  int b = bid;
  if (t < ODn) sobs[t] = obs[(b*NAn+i)*ODn + t];
  if (i > 0 && t < ADn) sap[t] = __ldcg(&g_aprev[b*ADn + t]);
  __syncthreads();
  int c = t;
  float x = be[c];
  if (i > 0){
    #pragma unroll
    for (int a=0;a<ADn;a++) x += sap[a]*We[a*DMn + c];
  }
  float cv = obs_rep[(b*NAn+i)*DMn + c];
  #pragma unroll 4
  for (int o=0;o<ODn;o++) cv += sobs[o]*Wo[o*DMn + c];
  __stcg(&g_x[b*DMn + c], x);
  __stcg(&g_ctx[b*DMn + c], cv);
  float2 mr = blockLN(x, red, t);
  __stcg(&g_xn[b*DMn + c], (x-mr.x)*mr.y*ln0[c]);
}

// ---------------- phase A: xn[128,512]@Win[512,2048] + conv/silu epilogue ----------------
__device__ __forceinline__ void phaseA(float* sm, int bid, int t,
    const float* __restrict__ Win, const float* __restrict__ cw,
    const float* __restrict__ cb, int inst, int step){
  int m0 = (bid>>5)*32, n0 = (bid&31)*64;
  float c[4];
  gemm32x64(sm, t, g_xn + m0*DMn, DMn, Win + n0, 2*DIn, DMn, c);
  int w=t>>5, lane=t&31, wm=w&1, wn=w>>1, gid=lane>>2, tg=lane&3;
  int slot = step & 3;
  #pragma unroll
  for (int r=0;r<2;r++){
    int m = m0 + wm*16 + gid + 8*r;
    int n = n0 + wn*8 + 2*tg;
    float v0 = c[2*r], v1 = c[2*r+1];
    if (n0 < DIn){
      int d = n;
      __stcg((float2*)&g_hist[((inst*4+slot)*Bn + m)*DIn + d], make_float2(v0,v1));
      float2 w3 = *(const float2*)&cw[3*DIn+d];
      float2 cbv = *(const float2*)&cb[d];
      float cx = cbv.x + w3.x*v0, cy = cbv.y + w3.y*v1;
      if (step>=1){ float2 h1=__ldcg((const float2*)&g_hist[((inst*4+((step-1)&3))*Bn+m)*DIn+d]);
                    float2 wv=*(const float2*)&cw[2*DIn+d]; cx+=wv.x*h1.x; cy+=wv.y*h1.y; }
      if (step>=2){ float2 h2=__ldcg((const float2*)&g_hist[((inst*4+((step-2)&3))*Bn+m)*DIn+d]);
                    float2 wv=*(const float2*)&cw[1*DIn+d]; cx+=wv.x*h2.x; cy+=wv.y*h2.y; }
      if (step>=3){ float2 h3=__ldcg((const float2*)&g_hist[((inst*4+((step-3)&3))*Bn+m)*DIn+d]);
                    float2 wv=*(const float2*)&cw[0*DIn+d]; cx+=wv.x*h3.x; cy+=wv.y*h3.y; }
      __stcg((float2*)&g_xc[m*DIn+d], make_float2(siluf_(cx), siluf_(cy)));
    } else {
      int d = n - DIn;
      __stcg((float2*)&g_sz[m*DIn+d], make_float2(siluf_(v0), siluf_(v1)));
    }
  }
}

// ---------------- phase B1: dbc partials, xc[128,1024]@Wx[1024,96], splitK=16, 128 blocks ----------------
__device__ __forceinline__ void phaseB1(float* sm, int bid, int t,
    const float* __restrict__ Wx){
  float* As = sm;          // [32][17] k-major, 544
  float* Bs = sm + 544;    // [32][96]
  int m0 = (bid>>4)*16, kz = bid&15, k0 = kz*64;
  int ty = t>>5, tx3 = (t&31)*3;
  float acc0=0.f, acc1=0.f, acc2=0.f;
  for (int kc=0; kc<64; kc+=32){
    { int m=t>>5, k=t&31;
      As[k*17+m] = __ldcg(&g_xc[(m0+m)*DIn + k0+kc + k]); }
    { int r=t>>4, c6=(t&15)*6;
      const float* wb = &Wx[(k0+kc+r)*96 + c6];
      float* bb = &Bs[r*96+c6];
      *(float2*)(bb+0)=*(const float2*)(wb+0);
      *(float2*)(bb+2)=*(const float2*)(wb+2);
      *(float2*)(bb+4)=*(const float2*)(wb+4); }
    __syncthreads();
    #pragma unroll
    for (int k=0;k<32;k++){
      float a = As[k*17+ty];
      acc0 += a*Bs[k*96+tx3];
      acc1 += a*Bs[k*96+tx3+1];
      acc2 += a*Bs[k*96+tx3+2];
    }
    __syncthreads();
  }
  float* P = g_dbcp[kz];
  __stcg(&P[(m0+ty)*96 + tx3],   acc0);
  __stcg(&P[(m0+ty)*96 + tx3+1], acc1);
  __stcg(&P[(m0+ty)*96 + tx3+2], acc2);
}

// ---------------- phase B2: reduce dbc -> delta -> SSM -> y*silu(z) ----------------
__device__ __forceinline__ void phaseB2(float* sm, int bid, int t,
    const float* __restrict__ Wdt, const float* __restrict__ dtb,
    const float* __restrict__ Dp, int inst, int step){
  float* sdbc = sm;          // [32][96]
  float* sWdt = sm + 3072;   // [32][32]
  float* snA  = sm + 4096;   // [32][32]
  int d0 = (bid&31)*32, b0 = (bid>>5)*32;
  #pragma unroll
  for (int u=0;u<2;u++){
    int e = t + 512*u;
    int r = e>>5, c = e&31;
    sWdt[r*32+c] = Wdt[r*DIn + d0 + c];
    snA[r*32+c]  = __ldcg(&g_negeA[inst*DIn*DSn + r*DIn + d0 + c]);
  }
  #pragma unroll
  for (int u=0;u<6;u++){
    int e = t + 512*u;
    int rr = e/96, cc = e - rr*96;
    float s = 0.f;
    #pragma unroll
    for (int p=0;p<16;p++) s += __ldcg(&g_dbcp[p][(b0+rr)*96 + cc]);
    sdbc[rr*96+cc] = s;
  }
  __syncthreads();
  int lane = t&31, br = t>>5;
  #pragma unroll
  for (int rep=0;rep<2;rep++){
    int brow = br + 16*rep;
    int b = b0 + brow, d = d0 + lane;
    float acc = dtb[d];
    #pragma unroll
    for (int r=0;r<DRn;r++) acc += sdbc[brow*96+r]*sWdt[r*32+lane];
    float delta = softplusf_(acc);
    float xc = __ldcg(&g_xc[b*DIn + d]);
    float dxc = delta*xc;
    float* hb = g_h + (size_t)inst*DSn*Bn*DIn + (size_t)b*DIn + d;
    float y = 0.f;
    #pragma unroll
    for (int s=0;s<DSn;s++){
      float dA = __expf(delta * snA[s*32+lane]);
      float hv = (step>0) ? __ldcg(&hb[(size_t)s*(Bn*DIn)]) : 0.f;
      hv = dA*hv + dxc*sdbc[brow*96+32+s];
      __stcg(&hb[(size_t)s*(Bn*DIn)], hv);
      y += hv*sdbc[brow*96+64+s];
    }
    y += Dp[d]*xc;
    __stcg(&g_ys[b*DIn + d], y*__ldcg(&g_sz[b*DIn + d]));
  }
  __syncthreads();
}

// ---------------- phase D: ys[128,1024]@Wout[1024,512], split-K=4 ----------------
__device__ __forceinline__ void phaseD(float* sm, int bid, int t,
    const float* __restrict__ Wout){
  int n0 = (bid&7)*64, m0 = ((bid>>3)&3)*32, kz = bid>>5;
  int k0 = kz*256;
  float c[4];
  gemm32x64(sm, t, g_ys + m0*DIn + k0, DIn, Wout + (size_t)k0*DMn + n0, DMn, 256, c);
  int w=t>>5, lane=t&31, wm=w&1, wn=w>>1, gid=lane>>2, tg=lane&3;
  float* P = g_part[kz];
  int n = n0 + wn*8 + 2*tg;
  int m = m0 + wm*16 + gid;
  __stcg((float2*)&P[m*DMn + n],     make_float2(c[0],c[1]));
  __stcg((float2*)&P[(m+8)*DMn + n], make_float2(c[2],c[3]));
}

// ---------------- phase AddLN: x += sum partials; g_xn = LN(x)*lnw (+ctx) ----------------
__device__ __forceinline__ void phaseAddLN(float* sm, int bid, int t,
    const float* __restrict__ lnw, int useCtx){
  float* red = sm;
  int b = bid, c = t;
  float x = __ldcg(&g_x[b*DMn + c]);
  #pragma unroll
  for (int p=0;p<4;p++) x += __ldcg(&g_part[p][b*DMn + c]);
  __stcg(&g_x[b*DMn + c], x);
  float2 mr = blockLN(x, red, t);
  float xn = (x-mr.x)*mr.y*lnw[c];
  if (useCtx) xn += __ldcg(&g_ctx[b*DMn + c]);
  __stcg(&g_xn[b*DMn + c], xn);
}

// ---------------- phase Head: head GEMM + raw/act/logprob ----------------
__device__ __forceinline__ void phaseHead(float* sm, int bid, int t,
    const float* __restrict__ Wh, const float* __restrict__ lstd,
    const float* __restrict__ eps, float* __restrict__ out, int i){
  float* sxn   = sm;
  float* spart = sm + 512;
  int b = bid;
  sxn[t] = __ldcg(&g_xn[b*DMn + t]);
  __syncthreads();
  int seg = t>>4, j = t&15;
  float p = 0.f;
  #pragma unroll 4
  for (int k=seg*16; k<seg*16+16; k++) p += sxn[k]*Wh[k*ADn + j];
  spart[t] = p;
  __syncthreads();
  if (t < 16){
    float m = 0.f;
    #pragma unroll
    for (int sg=0;sg<32;sg++) m += spart[sg*16 + t];
    float std = softplusf_(lstd[t]);
    float e = eps[(b*NAn+i)*ADn + t];
    float raw = m + std*e;
    float act = tanhf(raw);
    int oidx = (b*NAn+i)*ADn + t;
    out[oidx] = act;
    out[17408 + oidx] = raw;
    __stcg(&g_aprev[b*ADn + t], act);
    float term = -0.5f*e*e - logf(std)
               - 2.f*(0.69314718055994531f - raw - softplusf_(-2.f*raw));
    #pragma unroll
    for (int o=8;o;o>>=1) term += __shfl_xor_sync(0xffffu, term, o);
    if (t==0) out[16384 + b*NAn + i] = term - 0.5f*ADn*1.8378770664093453f;
  }
  __syncthreads();
}

// ---------------- the megakernel ----------------
__global__ void __launch_bounds__(NTHR, 1) mega(
    const float* __restrict__ obs_rep, const float* __restrict__ obs,
    const float* __restrict__ eps,
    const float* __restrict__ We, const float* __restrict__ be,
    const float* __restrict__ Wo,
    const float* __restrict__ ln1, const float* __restrict__ ln2,
    const float* __restrict__ ln_out,
    const float* __restrict__ Wh, const float* __restrict__ lstd,
    const float* __restrict__ ip_s, const float* __restrict__ cw_s,
    const float* __restrict__ cb_s, const float* __restrict__ xp_s,
    const float* __restrict__ dt_s, const float* __restrict__ dtb_s,
    const float* __restrict__ al_s, const float* __restrict__ D_s,
    const float* __restrict__ op_s,
    const float* __restrict__ ip_c, const float* __restrict__ cw_c,
    const float* __restrict__ cb_c, const float* __restrict__ xp_c,
    const float* __restrict__ dt_c, const float* __restrict__ dtb_c,
    const float* __restrict__ al_c, const float* __restrict__ D_c,
    const float* __restrict__ op_c,
    float* __restrict__ out){
  __shared__ __align__(16) float sm[9984];
  int bid = blockIdx.x, t = threadIdx.x;
  unsigned gen = g_gen;   // monotonic across graph replays

  // prep: -exp(A_log) transposed
  for (int idx = bid*NTHR + t; idx < 8*DIn*DSn; idx += NBLK*NTHR){
    int inst = idx >> 15;
    int e = idx & 32767;
    int d = e >> 5, s = e & 31;
    int v = inst & 1, nb = inst >> 1;
    const float* src = (v ? al_c : al_s) + nb*DIn*DSn;
    __stcg(&g_negeA[inst*DIn*DSn + s*DIn + d], -__expf(src[d*DSn + s]));
  }
  gridbar(gen, bid, t);

  for (int i=0;i<NAn;i++){
    phaseEmbed(sm, bid, t, obs_rep, obs, We, be, Wo, ln1, i);
    gridbar(gen, bid, t);
    for (int cell=0; cell<8; cell++){
      int nb = cell>>1, v = cell&1;
      const float* Win  = (v? ip_c : ip_s) + (size_t)nb*DMn*2*DIn;
      const float* cw   = (v? cw_c : cw_s) + nb*4*DIn;
      const float* cb   = (v? cb_c : cb_s) + nb*DIn;
      const float* Wx   = (v? xp_c : xp_s) + (size_t)nb*DIn*96;
      const float* Wdt  = (v? dt_c : dt_s) + nb*DRn*DIn;
      const float* dtb  = (v? dtb_c: dtb_s)+ nb*DIn;
      const float* Dp   = (v? D_c  : D_s)  + nb*DIn;
      const float* Wout = (v? op_c : op_s) + (size_t)nb*DIn*DMn;

      phaseA(sm, bid, t, Win, cw, cb, cell, i);
      gridbar(gen, bid, t);
      phaseB1(sm, bid, t, Wx);
      gridbar(gen, bid, t);
      phaseB2(sm, bid, t, Wdt, dtb, Dp, cell, i);
      gridbar(gen, bid, t);
      phaseD(sm, bid, t, Wout);
      gridbar(gen, bid, t);
      const float* lnw; int uc;
      if (v==0){ lnw = ln2 + nb*DMn; uc = 1; }
      else if (nb < NBn-1){ lnw = ln1 + (nb+1)*DMn; uc = 0; }
      else { lnw = ln_out; uc = 0; }
      phaseAddLN(sm, bid, t, lnw, uc);
      gridbar(gen, bid, t);
    }
    phaseHead(sm, bid, t, Wh, lstd, eps, out, i);
    gridbar(gen, bid, t);
  }
}

extern "C" void kernel_launch(void* const* d_in, const int* in_sizes, int n_in,
                              void* d_out, int out_size){
  (void)in_sizes; (void)n_in; (void)out_size;
  mega<<<NBLK, NTHR>>>(
    (const float*)d_in[0],  (const float*)d_in[1],  (const float*)d_in[2],
    (const float*)d_in[3],  (const float*)d_in[4],  (const float*)d_in[5],
    (const float*)d_in[6],  (const float*)d_in[7],  (const float*)d_in[8],
    (const float*)d_in[9],  (const float*)d_in[10],
    (const float*)d_in[11], (const float*)d_in[12], (const float*)d_in[13],
    (const float*)d_in[14], (const float*)d_in[15], (const float*)d_in[16],
    (const float*)d_in[17], (const float*)d_in[18], (const float*)d_in[19],
    (const float*)d_in[20], (const float*)d_in[21], (const float*)d_in[22],
    (const float*)d_in[23], (const float*)d_in[24], (const float*)d_in[25],
    (const float*)d_in[26], (const float*)d_in[27], (const float*)d_in[28],
    (float*)d_out);
}

// round 13
// speedup vs baseline: 1.3136x; 1.0339x over previous
#include <cuda_runtime.h>
#include <math.h>
#include <stdint.h>

#define Bn  128
#define NAn 8
#define ADn 16
#define DMn 512
#define DIn 1024
#define DSn 32
#define DRn 32
#define NBn 4
#define ODn 128
#define NBLK 128
#define NTHR 512

#define NWIN  (4*DMn*2*DIn)   // 4,194,304 per variant
#define NWOUT (4*DIn*DMn)     // 2,097,152 per variant

// ---------------- persistent scratch (no allocations allowed) ----------------
__device__ __align__(128) float g_x[Bn*DMn];
__device__ __align__(128) float g_ctx[Bn*DMn];
__device__ __align__(128) float g_xn[Bn*DMn];
__device__ __align__(128) float g_xnH[Bn*DMn];
__device__ __align__(128) float g_xnL[Bn*DMn];
__device__ __align__(128) float g_xc[Bn*DIn];
__device__ __align__(128) float g_sz[Bn*DIn];
__device__ __align__(128) float g_ysH[Bn*DIn];
__device__ __align__(128) float g_ysL[Bn*DIn];
__device__ __align__(128) float g_aprev[Bn*ADn];
__device__ __align__(128) float g_part[4][Bn*DMn];
__device__ __align__(128) float g_dbcp[16][Bn*96];
__device__ __align__(128) float g_hist[8*4*Bn*DIn];
__device__ __align__(128) float g_negeA[8*DIn*DSn];
__device__ __align__(128) float g_h[(size_t)8*DSn*Bn*DIn];
__device__ __align__(128) float g_WinH[2*NWIN];
__device__ __align__(128) float g_WinL[2*NWIN];
__device__ __align__(128) float g_WoutH[2*NWOUT];
__device__ __align__(128) float g_WoutL[2*NWOUT];
__device__ volatile unsigned g_flags[NBLK];  // zero-init
__device__ volatile unsigned g_gen;          // zero-init

__device__ __forceinline__ float sigmoidf_(float x){ return 1.f/(1.f+__expf(-x)); }
__device__ __forceinline__ float siluf_(float x){ return x*sigmoidf_(x); }
__device__ __forceinline__ float softplusf_(float x){ return (x>20.f)? x : log1pf(__expf(x)); }

__device__ __forceinline__ uint32_t tf32h(float x){
  uint32_t r; asm("cvt.rna.tf32.f32 %0, %1;" : "=r"(r) : "f"(x)); return r;
}
__device__ __forceinline__ void mma_tf32(float c[4], uint32_t a0,uint32_t a1,uint32_t a2,uint32_t a3,
                                         uint32_t b0,uint32_t b1){
  asm volatile("mma.sync.aligned.m16n8k8.row.col.f32.tf32.tf32.f32 "
    "{%0,%1,%2,%3},{%4,%5,%6,%7},{%8,%9},{%0,%1,%2,%3};"
    : "+f"(c[0]),"+f"(c[1]),"+f"(c[2]),"+f"(c[3])
    : "r"(a0),"r"(a1),"r"(a2),"r"(a3),"r"(b0),"r"(b1));
}

__device__ __forceinline__ void cp16(float* dst, const float* src){
  unsigned d = (unsigned)__cvta_generic_to_shared(dst);
  asm volatile("cp.async.cg.shared.global [%0], [%1], 16;" :: "r"(d), "l"(src));
}
__device__ __forceinline__ void cpcommit(){ asm volatile("cp.async.commit_group;" ::: "memory"); }

// ---------------- flag-array grid barrier (no atomic contention) ----------------
__device__ __forceinline__ void gridbar(unsigned& gen, int bid, int t){
  __syncthreads();
  gen++;
  if (t == 0){ __threadfence(); g_flags[bid] = gen; }
  if (bid == 0){
    if (t < NBLK){ while (g_flags[t] < gen) {} }
    __syncthreads();
    if (t == 0){ __threadfence(); g_gen = gen; }
  } else {
    if (t == 0){ while (g_gen < gen) {} __threadfence(); }
  }
  __syncthreads();
}

// ---------------- block-wide LayerNorm stats over 512 values (1/thread) ----------------
__device__ __forceinline__ float2 blockLN(float x, float* red, int t){
  float s = x, q = x*x;
  #pragma unroll
  for (int o=16;o;o>>=1){ s+=__shfl_xor_sync(0xffffffffu,s,o); q+=__shfl_xor_sync(0xffffffffu,q,o); }
  if ((t&31)==0){ red[t>>5]=s; red[16+(t>>5)]=q; }
  __syncthreads();
  if (t==0){
    float S=0,Q=0;
    #pragma unroll
    for (int w=0;w<16;w++){ S+=red[w]; Q+=red[16+w]; }
    float m=S*(1.f/DMn);
    red[32]=m; red[33]=rsqrtf(Q*(1.f/DMn)-m*m+1e-5f);
  }
  __syncthreads();
  float2 r = make_float2(red[32], red[33]);
  __syncthreads();
  return r;
}

// ============ pre-split tf32 3-term MMA GEMM, 32m x 64n tile, cp.async 3-stage ============
// smem floats: AhS 3x1152 @0, AlS 3x1152 @3456, BhS 3x2304 @6912, BlS 3x2304 @13824 (20736 total)
#define ASZ 1152
#define BSZ 2304
__device__ __forceinline__ void stageLoadHL(float* sm, int t, int s, int kc,
    const float* AH, const float* AL, int lda,
    const float* BH, const float* BL, int ldb){
  float* AhS = sm;            float* AlS = sm + 3*ASZ;
  float* BhS = sm + 6*ASZ;    float* BlS = sm + 6*ASZ + 3*BSZ;
  if (t < 256){
    int r = t>>3, c4 = (t&7)*4;
    cp16(AhS + s*ASZ + r*36 + c4, AH + r*lda + kc + c4);
  } else {
    int r = (t-256)>>3, c4 = (t&7)*4;
    cp16(AlS + s*ASZ + r*36 + c4, AL + r*lda + kc + c4);
  }
  { int r = t>>4, c4 = (t&15)*4;
    cp16(BhS + s*BSZ + r*72 + c4, BH + (size_t)(kc+r)*ldb + c4);
    cp16(BlS + s*BSZ + r*72 + c4, BL + (size_t)(kc+r)*ldb + c4); }
  cpcommit();
}

__device__ __forceinline__ void gemmHL(float* sm, int t,
    const float* AH, const float* AL, int lda,
    const float* BH, const float* BL, int ldb,
    int K, float c[4]){
  int w=t>>5, lane=t&31, wm=w&1, wn=w>>1, gid=lane>>2, tg=lane&3;
  c[0]=c[1]=c[2]=c[3]=0.f;
  int nch = K>>5;
  stageLoadHL(sm, t, 0, 0, AH, AL, lda, BH, BL, ldb);
  if (nch > 1) stageLoadHL(sm, t, 1, 32, AH, AL, lda, BH, BL, ldb);
  for (int ci=0; ci<nch; ci++){
    if (ci+2 < nch) asm volatile("cp.async.wait_group 1;" ::: "memory");
    else            asm volatile("cp.async.wait_group 0;" ::: "memory");
    __syncthreads();
    if (ci+2 < nch) stageLoadHL(sm, t, (ci+2)%3, (ci+2)*32, AH, AL, lda, BH, BL, ldb);
    const float* Ah = sm + (ci%3)*ASZ;
    const float* Al = sm + 3*ASZ + (ci%3)*ASZ;
    const float* Bh = sm + 6*ASZ + (ci%3)*BSZ;
    const float* Bl = sm + 6*ASZ + 3*BSZ + (ci%3)*BSZ;
    #pragma unroll
    for (int kk=0; kk<32; kk+=8){
      int ab = (wm*16+gid)*36 + kk + tg;
      uint32_t a0h=__float_as_uint(Ah[ab]),   a1h=__float_as_uint(Ah[ab+8*36]);
      uint32_t a2h=__float_as_uint(Ah[ab+4]), a3h=__float_as_uint(Ah[ab+4+8*36]);
      uint32_t a0l=__float_as_uint(Al[ab]),   a1l=__float_as_uint(Al[ab+8*36]);
      uint32_t a2l=__float_as_uint(Al[ab+4]), a3l=__float_as_uint(Al[ab+4+8*36]);
      int bb = (kk+tg)*72 + wn*8 + gid;
      uint32_t b0h=__float_as_uint(Bh[bb]), b1h=__float_as_uint(Bh[bb+4*72]);
      uint32_t b0l=__float_as_uint(Bl[bb]), b1l=__float_as_uint(Bl[bb+4*72]);
      mma_tf32(c, a0h,a1h,a2h,a3h, b0h,b1h);
      mma_tf32(c, a0l,a1l,a2l,a3l, b0h,b1h);
      mma_tf32(c, a0h,a1h,a2h,a3h, b0l,b1l);
    }
    __syncthreads();
  }
}

// ---------------- phase: embed + ctx + LN -> xn (plain + hi/lo) ----------------
__device__ __forceinline__ void phaseEmbed(float* sm, int bid, int t,
    const float* __restrict__ obs_rep, const float* __restrict__ obs,
    const float* __restrict__ We, const float* __restrict__ be,
    const float* __restrict__ Wo, const float* __restrict__ ln0, int i){
  float* sobs = sm;
  float* sap  = sm + 128;
  float* red  = sm + 160;
  int b = bid;
  if (t < ODn) sobs[t] = obs[(b*NAn+i)*ODn + t];
  if (i > 0 && t < ADn) sap[t] = __ldcg(&g_aprev[b*ADn + t]);
  __syncthreads();
  int c = t;
  float x = be[c];
  if (i > 0){
    #pragma unroll
    for (int a=0;a<ADn;a++) x += sap[a]*We[a*DMn + c];
  }
  float cv = obs_rep[(b*NAn+i)*DMn + c];
  #pragma unroll 4
  for (int o=0;o<ODn;o++) cv += sobs[o]*Wo[o*DMn + c];
  __stcg(&g_x[b*DMn + c], x);
  __stcg(&g_ctx[b*DMn + c], cv);
  float2 mr = blockLN(x, red, t);
  float xn = (x-mr.x)*mr.y*ln0[c];
  uint32_t h = tf32h(xn);
  __stcg(&g_xnH[b*DMn + c], __uint_as_float(h));
  __stcg(&g_xnL[b*DMn + c], __uint_as_float(tf32h(xn-__uint_as_float(h))));
}

// ---------------- phase A: xn[128,512]@Win[512,2048] + conv/silu epilogue ----------------
__device__ __forceinline__ void phaseA(float* sm, int bid, int t,
    const float* __restrict__ WinH, const float* __restrict__ WinL,
    const float* __restrict__ cw, const float* __restrict__ cb,
    int inst, int step){
  int m0 = (bid>>5)*32, n0 = (bid&31)*64;
  float c[4];
  gemmHL(sm, t, g_xnH + m0*DMn, g_xnL + m0*DMn, DMn, WinH + n0, WinL + n0, 2*DIn, DMn, c);
  int w=t>>5, lane=t&31, wm=w&1, wn=w>>1, gid=lane>>2, tg=lane&3;
  int slot = step & 3;
  #pragma unroll
  for (int r=0;r<2;r++){
    int m = m0 + wm*16 + gid + 8*r;
    int n = n0 + wn*8 + 2*tg;
    float v0 = c[2*r], v1 = c[2*r+1];
    if (n0 < DIn){
      int d = n;
      __stcg((float2*)&g_hist[((inst*4+slot)*Bn + m)*DIn + d], make_float2(v0,v1));
      float2 w3 = *(const float2*)&cw[3*DIn+d];
      float2 cbv = *(const float2*)&cb[d];
      float cx = cbv.x + w3.x*v0, cy = cbv.y + w3.y*v1;
      if (step>=1){ float2 h1=__ldcg((const float2*)&g_hist[((inst*4+((step-1)&3))*Bn+m)*DIn+d]);
                    float2 wv=*(const float2*)&cw[2*DIn+d]; cx+=wv.x*h1.x; cy+=wv.y*h1.y; }
      if (step>=2){ float2 h2=__ldcg((const float2*)&g_hist[((inst*4+((step-2)&3))*Bn+m)*DIn+d]);
                    float2 wv=*(const float2*)&cw[1*DIn+d]; cx+=wv.x*h2.x; cy+=wv.y*h2.y; }
      if (step>=3){ float2 h3=__ldcg((const float2*)&g_hist[((inst*4+((step-3)&3))*Bn+m)*DIn+d]);
                    float2 wv=*(const float2*)&cw[0*DIn+d]; cx+=wv.x*h3.x; cy+=wv.y*h3.y; }
      __stcg((float2*)&g_xc[m*DIn+d], make_float2(siluf_(cx), siluf_(cy)));
    } else {
      int d = n - DIn;
      __stcg((float2*)&g_sz[m*DIn+d], make_float2(siluf_(v0), siluf_(v1)));
    }
  }
}

// ---------------- phase B1: dbc partials, xc[128,1024]@Wx[1024,96], splitK=16, 128 blocks ----------------
__device__ __forceinline__ void phaseB1(float* sm, int bid, int t,
    const float* __restrict__ Wx){
  float* As = sm;          // [32][17] k-major
  float* Bs = sm + 544;    // [32][96]
  int m0 = (bid>>4)*16, kz = bid&15, k0 = kz*64;
  int ty = t>>5, tx3 = (t&31)*3;
  float acc0=0.f, acc1=0.f, acc2=0.f;
  for (int kc=0; kc<64; kc+=32){
    { int m=t>>5, k=t&31;
      As[k*17+m] = __ldcg(&g_xc[(m0+m)*DIn + k0+kc + k]); }
    { int r=t>>4, c6=(t&15)*6;
      const float* wb = &Wx[(k0+kc+r)*96 + c6];
      float* bb = &Bs[r*96+c6];
      *(float2*)(bb+0)=*(const float2*)(wb+0);
      *(float2*)(bb+2)=*(const float2*)(wb+2);
      *(float2*)(bb+4)=*(const float2*)(wb+4); }
    __syncthreads();
    #pragma unroll
    for (int k=0;k<32;k++){
      float a = As[k*17+ty];
      acc0 += a*Bs[k*96+tx3];
      acc1 += a*Bs[k*96+tx3+1];
      acc2 += a*Bs[k*96+tx3+2];
    }
    __syncthreads();
  }
  float* P = g_dbcp[kz];
  __stcg(&P[(m0+ty)*96 + tx3],   acc0);
  __stcg(&P[(m0+ty)*96 + tx3+1], acc1);
  __stcg(&P[(m0+ty)*96 + tx3+2], acc2);
}

// ---------------- phase B2: reduce dbc -> delta -> SSM -> ys (hi/lo) ----------------
__device__ __forceinline__ void phaseB2(float* sm, int bid, int t,
    const float* __restrict__ Wdt, const float* __restrict__ dtb,
    const float* __restrict__ Dp, int inst, int step){
  float* sdbc = sm;          // [32][96]
  float* sWdt = sm + 3072;   // [32][32]
  float* snA  = sm + 4096;   // [32][32]
  int d0 = (bid&31)*32, b0 = (bid>>5)*32;
  #pragma unroll
  for (int u=0;u<2;u++){
    int e = t + 512*u;
    int r = e>>5, c = e&31;
    sWdt[r*32+c] = Wdt[r*DIn + d0 + c];
    snA[r*32+c]  = __ldcg(&g_negeA[inst*DIn*DSn + r*DIn + d0 + c]);
  }
  #pragma unroll
  for (int u=0;u<6;u++){
    int e = t + 512*u;
    int rr = e/96, cc = e - rr*96;
    float s = 0.f;
    #pragma unroll
    for (int p=0;p<16;p++) s += __ldcg(&g_dbcp[p][(b0+rr)*96 + cc]);
    sdbc[rr*96+cc] = s;
  }
  __syncthreads();
  int lane = t&31, br = t>>5;
  #pragma unroll
  for (int rep=0;rep<2;rep++){
    int brow = br + 16*rep;
    int b = b0 + brow, d = d0 + lane;
    float acc = dtb[d];
    #pragma unroll
    for (int r=0;r<DRn;r++) acc += sdbc[brow*96+r]*sWdt[r*32+lane];
    float delta = softplusf_(acc);
    float xc = __ldcg(&g_xc[b*DIn + d]);
    float dxc = delta*xc;
    float* hb = g_h + (size_t)inst*DSn*Bn*DIn + (size_t)b*DIn + d;
    float y = 0.f;
    #pragma unroll
    for (int s=0;s<DSn;s++){
      float dA = __expf(delta * snA[s*32+lane]);
      float hv = (step>0) ? __ldcg(&hb[(size_t)s*(Bn*DIn)]) : 0.f;
      hv = dA*hv + dxc*sdbc[brow*96+32+s];
      __stcg(&hb[(size_t)s*(Bn*DIn)], hv);
      y += hv*sdbc[brow*96+64+s];
    }
    y += Dp[d]*xc;
    float ys = y*__ldcg(&g_sz[b*DIn + d]);
    uint32_t h = tf32h(ys);
    __stcg(&g_ysH[b*DIn + d], __uint_as_float(h));
    __stcg(&g_ysL[b*DIn + d], __uint_as_float(tf32h(ys-__uint_as_float(h))));
  }
  __syncthreads();
}

// ---------------- phase D: ys[128,1024]@Wout[1024,512], split-K=4 ----------------
__device__ __forceinline__ void phaseD(float* sm, int bid, int t,
    const float* __restrict__ WoutH, const float* __restrict__ WoutL){
  int n0 = (bid&7)*64, m0 = ((bid>>3)&3)*32, kz = bid>>5;
  int k0 = kz*256;
  float c[4];
  gemmHL(sm, t, g_ysH + m0*DIn + k0, g_ysL + m0*DIn + k0, DIn,
         WoutH + (size_t)k0*DMn + n0, WoutL + (size_t)k0*DMn + n0, DMn, 256, c);
  int w=t>>5, lane=t&31, wm=w&1, wn=w>>1, gid=lane>>2, tg=lane&3;
  float* P = g_part[kz];
  int n = n0 + wn*8 + 2*tg;
  int m = m0 + wm*16 + gid;
  __stcg((float2*)&P[m*DMn + n],     make_float2(c[0],c[1]));
  __stcg((float2*)&P[(m+8)*DMn + n], make_float2(c[2],c[3]));
}

// ---------------- phase AddLN: x += sum partials; xn = LN(x)*lnw (+ctx), plain+hi/lo ----------------
__device__ __forceinline__ void phaseAddLN(float* sm, int bid, int t,
    const float* __restrict__ lnw, int useCtx){
  float* red = sm;
  int b = bid, c = t;
  float x = __ldcg(&g_x[b*DMn + c]);
  #pragma unroll
  for (int p=0;p<4;p++) x += __ldcg(&g_part[p][b*DMn + c]);
  __stcg(&g_x[b*DMn + c], x);
  float2 mr = blockLN(x, red, t);
  float xn = (x-mr.x)*mr.y*lnw[c];
  if (useCtx) xn += __ldcg(&g_ctx[b*DMn + c]);
  __stcg(&g_xn[b*DMn + c], xn);
  uint32_t h = tf32h(xn);
  __stcg(&g_xnH[b*DMn + c], __uint_as_float(h));
  __stcg(&g_xnL[b*DMn + c], __uint_as_float(tf32h(xn-__uint_as_float(h))));
}

// ---------------- phase Head: head GEMM + raw/act/logprob ----------------
__device__ __forceinline__ void phaseHead(float* sm, int bid, int t,
    const float* __restrict__ Wh, const float* __restrict__ lstd,
    const float* __restrict__ eps, float* __restrict__ out, int i){
  float* sxn   = sm;
  float* spart = sm + 512;
  int b = bid;
  sxn[t] = __ldcg(&g_xn[b*DMn + t]);
  __syncthreads();
  int seg = t>>4, j = t&15;
  float p = 0.f;
  #pragma unroll 4
  for (int k=seg*16; k<seg*16+16; k++) p += sxn[k]*Wh[k*ADn + j];
  spart[t] = p;
  __syncthreads();
  if (t < 16){
    float m = 0.f;
    #pragma unroll
    for (int sg=0;sg<32;sg++) m += spart[sg*16 + t];
    float std = softplusf_(lstd[t]);
    float e = eps[(b*NAn+i)*ADn + t];
    float raw = m + std*e;
    float act = tanhf(raw);
    int oidx = (b*NAn+i)*ADn + t;
    out[oidx] = act;
    out[17408 + oidx] = raw;
    __stcg(&g_aprev[b*ADn + t], act);
    float term = -0.5f*e*e - logf(std)
               - 2.f*(0.69314718055994531f - raw - softplusf_(-2.f*raw));
    #pragma unroll
    for (int o=8;o;o>>=1) term += __shfl_xor_sync(0xffffu, term, o);
    if (t==0) out[16384 + b*NAn + i] = term - 0.5f*ADn*1.8378770664093453f;
  }
  __syncthreads();
}

// ---------------- the megakernel ----------------
__global__ void __launch_bounds__(NTHR, 1) mega(
    const float* __restrict__ obs_rep, const float* __restrict__ obs,
    const float* __restrict__ eps,
    const float* __restrict__ We, const float* __restrict__ be,
    const float* __restrict__ Wo,
    const float* __restrict__ ln1, const float* __restrict__ ln2,
    const float* __restrict__ ln_out,
    const float* __restrict__ Wh, const float* __restrict__ lstd,
    const float* __restrict__ ip_s, const float* __restrict__ cw_s,
    const float* __restrict__ cb_s, const float* __restrict__ xp_s,
    const float* __restrict__ dt_s, const float* __restrict__ dtb_s,
    const float* __restrict__ al_s, const float* __restrict__ D_s,
    const float* __restrict__ op_s,
    const float* __restrict__ ip_c, const float* __restrict__ cw_c,
    const float* __restrict__ cb_c, const float* __restrict__ xp_c,
    const float* __restrict__ dt_c, const float* __restrict__ dtb_c,
    const float* __restrict__ al_c, const float* __restrict__ D_c,
    const float* __restrict__ op_c,
    float* __restrict__ out){
  extern __shared__ __align__(16) float sm[];
  int bid = blockIdx.x, t = threadIdx.x;
  unsigned gen = g_gen;   // monotonic across graph replays
  int gtid = bid*NTHR + t;

  // prep 1: -exp(A_log) transposed
  for (int idx = gtid; idx < 8*DIn*DSn; idx += NBLK*NTHR){
    int inst = idx >> 15;
    int e = idx & 32767;
    int d = e >> 5, s = e & 31;
    int v = inst & 1, nb = inst >> 1;
    const float* src = (v ? al_c : al_s) + nb*DIn*DSn;
    __stcg(&g_negeA[inst*DIn*DSn + s*DIn + d], -__expf(src[d*DSn + s]));
  }
  // prep 2: hi/lo split of Win (both variants)
  for (int idx = gtid; idx < 2*NWIN; idx += NBLK*NTHR){
    float wv = (idx < NWIN) ? ip_s[idx] : ip_c[idx-NWIN];
    uint32_t h = tf32h(wv);
    g_WinH[idx] = __uint_as_float(h);
    g_WinL[idx] = __uint_as_float(tf32h(wv - __uint_as_float(h)));
  }
  // prep 3: hi/lo split of Wout
  for (int idx = gtid; idx < 2*NWOUT; idx += NBLK*NTHR){
    float wv = (idx < NWOUT) ? op_s[idx] : op_c[idx-NWOUT];
    uint32_t h = tf32h(wv);
    g_WoutH[idx] = __uint_as_float(h);
    g_WoutL[idx] = __uint_as_float(tf32h(wv - __uint_as_float(h)));
  }
  gridbar(gen, bid, t);

  for (int i=0;i<NAn;i++){
    phaseEmbed(sm, bid, t, obs_rep, obs, We, be, Wo, ln1, i);
    gridbar(gen, bid, t);
    for (int cell=0; cell<8; cell++){
      int nb = cell>>1, v = cell&1;
      const float* WinH = g_WinH + (size_t)v*NWIN + (size_t)nb*DMn*2*DIn;
      const float* WinL = g_WinL + (size_t)v*NWIN + (size_t)nb*DMn*2*DIn;
      const float* WoutH= g_WoutH + (size_t)v*NWOUT + (size_t)nb*DIn*DMn;
      const float* WoutL= g_WoutL + (size_t)v*NWOUT + (size_t)nb*DIn*DMn;
      const float* cw   = (v? cw_c : cw_s) + nb*4*DIn;
      const float* cb   = (v? cb_c : cb_s) + nb*DIn;
      const float* Wx   = (v? xp_c : xp_s) + (size_t)nb*DIn*96;
      const float* Wdt  = (v? dt_c : dt_s) + nb*DRn*DIn;
      const float* dtb  = (v? dtb_c: dtb_s)+ nb*DIn;
      const float* Dp   = (v? D_c  : D_s)  + nb*DIn;

      phaseA(sm, bid, t, WinH, WinL, cw, cb, cell, i);
      gridbar(gen, bid, t);
      phaseB1(sm, bid, t, Wx);
      gridbar(gen, bid, t);
      phaseB2(sm, bid, t, Wdt, dtb, Dp, cell, i);
      gridbar(gen, bid, t);
      phaseD(sm, bid, t, WoutH, WoutL);
      gridbar(gen, bid, t);
      const float* lnw; int uc;
      if (v==0){ lnw = ln2 + nb*DMn; uc = 1; }
      else if (nb < NBn-1){ lnw = ln1 + (nb+1)*DMn; uc = 0; }
      else { lnw = ln_out; uc = 0; }
      phaseAddLN(sm, bid, t, lnw, uc);
      gridbar(gen, bid, t);
    }
    phaseHead(sm, bid, t, Wh, lstd, eps, out, i);
    gridbar(gen, bid, t);
  }
}

extern "C" void kernel_launch(void* const* d_in, const int* in_sizes, int n_in,
                              void* d_out, int out_size){
  (void)in_sizes; (void)n_in; (void)out_size;
  const size_t smemBytes = 20736u * sizeof(float);   // 82944 B
  cudaFuncSetAttribute(mega, cudaFuncAttributeMaxDynamicSharedMemorySize, (int)smemBytes);
  mega<<<NBLK, NTHR, smemBytes>>>(
    (const float*)d_in[0],  (const float*)d_in[1],  (const float*)d_in[2],
    (const float*)d_in[3],  (const float*)d_in[4],  (const float*)d_in[5],
    (const float*)d_in[6],  (const float*)d_in[7],  (const float*)d_in[8],
    (const float*)d_in[9],  (const float*)d_in[10],
    (const float*)d_in[11], (const float*)d_in[12], (const float*)d_in[13],
    (const float*)d_in[14], (const float*)d_in[15], (const float*)d_in[16],
    (const float*)d_in[17], (const float*)d_in[18], (const float*)d_in[19],
    (const float*)d_in[20], (const float*)d_in[21], (const float*)d_in[22],
    (const float*)d_in[23], (const float*)d_in[24], (const float*)d_in[25],
    (const float*)d_in[26], (const float*)d_in[27], (const float*)d_in[28],
    (float*)d_out);
}